// round 5
// baseline (speedup 1.0000x reference)
#include <cuda_runtime.h>
#include <cstdint>

#define NQ 4
#define NL 8
#define NBLOCKS 592   // 148 SMs x 4 CTAs: one persistent wave

__device__ __forceinline__ float2 cmul(float2 a, float2 b) {
    return make_float2(fmaf(a.x, b.x, -a.y * b.y), fmaf(a.x, b.y, a.y * b.x));
}
__device__ __forceinline__ float2 cfma(float2 a, float2 b, float2 acc) {
    acc.x = fmaf(a.x, b.x, fmaf(-a.y, b.y, acc.x));
    acc.y = fmaf(a.x, b.y, fmaf(a.y, b.x, acc.y));
    return acc;
}

// CNOT state-index map: flips target bit if control bit set.
__device__ __forceinline__ int cnot_map(int m, int c, int t) {
    int bc = 3 - c, bt = 3 - t;
    if ((m >> bc) & 1) m ^= (1 << bt);
    return m;
}

// Fused kernel: every block builds the 81-coefficient tensor T in shared
// (redundantly, ~2.5us parallel prologue), then grid-strides over samples.
__global__ void __launch_bounds__(256, 4) vqc_fused(const float4* __restrict__ x,
                                                    const float* __restrict__ w,
                                                    float* __restrict__ out, int n) {
    __shared__ float2 sGate[NL * NQ][4];   // 2x2 Rot matrices
    __shared__ float2 sPA[NL][16];         // g(w0) (x) g(w1), per layer
    __shared__ float2 sPB[NL][16];         // g(w2) (x) g(w3), per layer
    __shared__ float2 sUa[256], sUb[256];  // U[col][m] ping-pong
    __shared__ float  sG[256];             // real G reindexed by wire pair-codes
    __shared__ float  sA1[192], sA2[144];  // Tucker staging
    __shared__ __align__(16) float sT[112];  // final 27x4 table

    const int t = threadIdx.x;

    // ================= SETUP PHASE (all blocks, redundant) =================
    // ---- phase 0: gate matrices (t<32) + identity init ----
    if (t < NL * NQ) {
        float phi = w[t * 3 + 0], th = w[t * 3 + 1], om = w[t * 3 + 2];
        float st, ct; __sincosf(0.5f * th, &st, &ct);
        float a = 0.5f * (phi + om), b = 0.5f * (phi - om);
        float sa, ca, sb, cb;
        __sincosf(a, &sa, &ca);
        __sincosf(b, &sb, &cb);
        sGate[t][0] = make_float2(ca * ct, -sa * ct);   // m00 = e^{-ia} ct
        sGate[t][1] = make_float2(-cb * st, -sb * st);  // m01 = -e^{+ib} st
        sGate[t][2] = make_float2(cb * st, -sb * st);   // m10 = e^{-ib} st
        sGate[t][3] = make_float2(ca * ct, sa * ct);    // m11 = e^{+ia} ct
    }
    {
        int col = t >> 4, m = t & 15;
        sUa[t] = make_float2(col == m ? 1.0f : 0.0f, 0.0f);
    }
    __syncthreads();

    // ---- phase 1: pair Kronecker factors, one entry per thread ----
    {
        int l = t >> 5, r = t & 31;
        int which = r >> 4, idx = r & 15;
        int i = idx >> 2, j = idx & 3;
        const float2* gA = sGate[l * 4 + which * 2 + 0];
        const float2* gB = sGate[l * 4 + which * 2 + 1];
        float2 v = cmul(gA[(i >> 1) * 2 + (j >> 1)], gB[(i & 1) * 2 + (j & 1)]);
        if (which) sPB[l][idx] = v; else sPA[l][idx] = v;
    }
    __syncthreads();

    // ---- phase 2: 8 layers, 1 sync each; CNOT ring folded into write index ----
    {
        float2* cur = sUa;
        float2* nxt = sUb;
        const int col = t >> 4, m = t & 15;
        const int mh = m >> 2, ml = m & 3;
        int mp = m;
        mp = cnot_map(mp, 0, 1);
        mp = cnot_map(mp, 1, 2);
        mp = cnot_map(mp, 2, 3);
        mp = cnot_map(mp, 3, 0);
        for (int l = 0; l < NL; l++) {
            float2 acc = make_float2(0.0f, 0.0f);
#pragma unroll
            for (int nh = 0; nh < 4; nh++) {
                float2 inner = make_float2(0.0f, 0.0f);
#pragma unroll
                for (int nl = 0; nl < 4; nl++)
                    inner = cfma(sPB[l][ml * 4 + nl], cur[col * 16 + nh * 4 + nl], inner);
                acc = cfma(sPA[l][mh * 4 + nh], inner, acc);
            }
            nxt[col * 16 + mp] = acc;
            __syncthreads();
            float2* tmp = cur; cur = nxt; nxt = tmp;
        }
        // after even number of swaps (NL=8), result is back in sUa
    }

    // ---- phase 3: H = U^dag Z0 U, phase-fold to real G ----
    {
        const float2* U = sUa;
        int j = t >> 4, k = t & 15;
        float hr = 0.0f, hi = 0.0f;
#pragma unroll
        for (int mm = 0; mm < 16; mm++) {
            float zz = ((mm >> 3) & 1) ? -1.0f : 1.0f;
            float2 uj = U[j * 16 + mm], uk = U[k * 16 + mm];
            hr += zz * (uj.x * uk.x + uj.y * uk.y);
            hi += zz * (uj.x * uk.y - uj.y * uk.x);
        }
        int q = (__popc(j) - __popc(k)) & 3;  // i^q * H, take Re
        float gval = (q == 0) ? hr : (q == 1) ? -hi : (q == 2) ? -hr : hi;
        int gidx = 0;
#pragma unroll
        for (int wq = 0; wq < 4; wq++) {
            int bi = 3 - wq;
            int p = ((j >> bi) & 1) * 2 + ((k >> bi) & 1);
            gidx = gidx * 4 + p;
        }
        sG[gidx] = gval;
    }
    __syncthreads();

    // ---- phase 4: Tucker contract each wire's pair-code (4) with V (4x3) ----
    const float V[4][3] = {{0.5f, 0.5f, 0.0f},
                           {0.0f, 0.0f, 0.5f},
                           {0.0f, 0.0f, 0.5f},
                           {0.5f, -0.5f, 0.0f}};
    if (t < 192) {  // A1[p0][p1][p2][d]
        int d = t % 3, p2 = (t / 3) & 3, p1 = (t / 12) & 3, p0 = t / 48;
        float acc = 0.0f;
#pragma unroll
        for (int p3 = 0; p3 < 4; p3++)
            acc += sG[((p0 * 4 + p1) * 4 + p2) * 4 + p3] * V[p3][d];
        sA1[t] = acc;
    }
    __syncthreads();
    if (t < 144) {  // A2[p0][p1][c][d]
        int d = t % 3, c = (t / 3) % 3, rest = t / 9;
        int p1 = rest & 3, p0 = rest >> 2;
        float acc = 0.0f;
#pragma unroll
        for (int p2 = 0; p2 < 4; p2++)
            acc += sA1[((p0 * 4 + p1) * 4 + p2) * 3 + d] * V[p2][c];
        sA2[t] = acc;
    }
    __syncthreads();
    if (t < 108) {  // A3[p0][b][c][d] (reuse sA1)
        int d = t % 3, c = (t / 3) % 3, b = (t / 9) % 3, p0 = t / 27;
        float acc = 0.0f;
#pragma unroll
        for (int p1 = 0; p1 < 4; p1++)
            acc += sA2[((p0 * 4 + p1) * 3 + c) * 3 + d] * V[p1][b];
        sA1[t] = acc;
    }
    __syncthreads();
    if (t < 81) {  // T[a][b][c][d] -> sT[(a*9+b*3+c)*4 + d]
        int d = t % 3, c = (t / 3) % 3, b = (t / 9) % 3, a = t / 27;
        float acc = 0.0f;
#pragma unroll
        for (int p0 = 0; p0 < 4; p0++)
            acc += sA1[((p0 * 3 + b) * 3 + c) * 3 + d] * V[p0][a];
        sT[(a * 9 + b * 3 + c) * 4 + d] = acc;
    } else if (t < 108) {
        sT[(t - 81) * 4 + 3] = 0.0f;  // pad lanes
    }
    __syncthreads();

    // ================= MAIN PHASE: grid-stride over quads =================
    // E = sum_u f0[a(u)] f1[b(u)] * (T-row(u) . (f2 x f3)),  f = (1, cos, sin)
    const float4* sTv = reinterpret_cast<const float4*>(sT);
    const int quads = (n + 3) >> 2;
    const int stride = gridDim.x * 256;

    for (int q = blockIdx.x * 256 + t; q < quads; q += stride) {
        const int base = q * 4;
        const bool full = (base + 3 < n);

        float c0[4], s0[4], c1[4], s1[4], c2[4], s2[4], c3[4], s3[4];
#pragma unroll
        for (int k = 0; k < 4; k++) {
            float4 v = (full || base + k < n) ? x[base + k]
                                              : make_float4(0.f, 0.f, 0.f, 0.f);
            __sincosf(v.x, &s0[k], &c0[k]);
            __sincosf(v.y, &s1[k], &c1[k]);
            __sincosf(v.z, &s2[k], &c2[k]);
            __sincosf(v.w, &s3[k], &c3[k]);
        }

        float E[4];
#pragma unroll
        for (int u = 0; u < 9; u++) {
            const float4 t0 = sTv[u * 3 + 0];
            const float4 t1 = sTv[u * 3 + 1];
            const float4 t2 = sTv[u * 3 + 2];
            const int a = u / 3, b = u % 3;  // compile-time under unroll
#pragma unroll
            for (int k = 0; k < 4; k++) {
                float a0 = fmaf(t0.z, s3[k], fmaf(t0.y, c3[k], t0.x));
                float a1 = fmaf(t1.z, s3[k], fmaf(t1.y, c3[k], t1.x));
                float a2 = fmaf(t2.z, s3[k], fmaf(t2.y, c3[k], t2.x));
                float r  = fmaf(a2, s2[k], fmaf(a1, c2[k], a0));
                if (a == 0 && b == 0) {
                    E[k] = r;
                } else if (a == 0) {
                    E[k] = fmaf(r, (b == 1) ? c1[k] : s1[k], E[k]);
                } else if (b == 0) {
                    E[k] = fmaf(r, (a == 1) ? c0[k] : s0[k], E[k]);
                } else {
                    float f0v = (a == 1) ? c0[k] : s0[k];
                    float f1v = (b == 1) ? c1[k] : s1[k];
                    E[k] = fmaf(r * f0v, f1v, E[k]);
                }
            }
        }

        if (full) {
            reinterpret_cast<float4*>(out)[q] = make_float4(E[0], E[1], E[2], E[3]);
        } else {
#pragma unroll
            for (int k = 0; k < 4; k++)
                if (base + k < n) out[base + k] = E[k];
        }
    }
}

extern "C" void kernel_launch(void* const* d_in, const int* in_sizes, int n_in,
                              void* d_out, int out_size) {
    const float* x = (const float*)d_in[0];        // (B, 4)
    const float* w = (const float*)d_in[1];        // (8, 4, 3)
    float* out = (float*)d_out;                    // (B,)
    int n = out_size;                              // B

    int quads = (n + 3) / 4;
    int blocks_needed = (quads + 255) / 256;
    int blocks = blocks_needed < NBLOCKS ? blocks_needed : NBLOCKS;
    vqc_fused<<<blocks, 256>>>((const float4*)x, w, out, n);
}

// round 6
// speedup vs baseline: 1.3770x; 1.3770x over previous
#include <cuda_runtime.h>
#include <cstdint>

#define NQ 4
#define NL 8

// 27 groups (a*9+b*3+c) x 4 floats (d=0..2, pad). Written by setup, read by main.
__device__ __align__(16) float g_T[112];

__device__ __forceinline__ float2 cmul(float2 a, float2 b) {
    return make_float2(fmaf(a.x, b.x, -a.y * b.y), fmaf(a.x, b.y, a.y * b.x));
}
__device__ __forceinline__ float2 cfma(float2 a, float2 b, float2 acc) {
    acc.x = fmaf(a.x, b.x, fmaf(-a.y, b.y, acc.x));
    acc.y = fmaf(a.x, b.y, fmaf(a.y, b.x, acc.y));
    return acc;
}

// CNOT state-index map: flips target bit if control bit set.
__device__ __forceinline__ int cnot_map(int m, int c, int t) {
    int bc = 3 - c, bt = 3 - t;
    if ((m >> bc) & 1) m ^= (1 << bt);
    return m;
}

// One block, 256 threads. Builds the 81-coefficient multilinear tensor T.
__global__ void vqc_setup(const float* __restrict__ w) {
    __shared__ float2 sGate[NL * NQ][4];
    __shared__ float2 sPA[NL][16];
    __shared__ float2 sPB[NL][16];
    __shared__ float2 sUa[256], sUb[256];
    __shared__ float  sG[256];
    __shared__ float  sA1[192], sA2[144];

    const int t = threadIdx.x;

    if (t < NL * NQ) {
        float phi = w[t * 3 + 0], th = w[t * 3 + 1], om = w[t * 3 + 2];
        float st, ct; __sincosf(0.5f * th, &st, &ct);
        float a = 0.5f * (phi + om), b = 0.5f * (phi - om);
        float sa, ca, sb, cb;
        __sincosf(a, &sa, &ca);
        __sincosf(b, &sb, &cb);
        sGate[t][0] = make_float2(ca * ct, -sa * ct);
        sGate[t][1] = make_float2(-cb * st, -sb * st);
        sGate[t][2] = make_float2(cb * st, -sb * st);
        sGate[t][3] = make_float2(ca * ct, sa * ct);
    }
    {
        int col = t >> 4, m = t & 15;
        sUa[t] = make_float2(col == m ? 1.0f : 0.0f, 0.0f);
    }
    __syncthreads();

    {
        int l = t >> 5, r = t & 31;
        int which = r >> 4, idx = r & 15;
        int i = idx >> 2, j = idx & 3;
        const float2* gA = sGate[l * 4 + which * 2 + 0];
        const float2* gB = sGate[l * 4 + which * 2 + 1];
        float2 v = cmul(gA[(i >> 1) * 2 + (j >> 1)], gB[(i & 1) * 2 + (j & 1)]);
        if (which) sPB[l][idx] = v; else sPA[l][idx] = v;
    }
    __syncthreads();

    float2* cur = sUa;
    float2* nxt = sUb;
    const int col = t >> 4, m = t & 15;
    const int mh = m >> 2, ml = m & 3;
    int mp = m;
    mp = cnot_map(mp, 0, 1);
    mp = cnot_map(mp, 1, 2);
    mp = cnot_map(mp, 2, 3);
    mp = cnot_map(mp, 3, 0);
    for (int l = 0; l < NL; l++) {
        float2 acc = make_float2(0.0f, 0.0f);
#pragma unroll
        for (int nh = 0; nh < 4; nh++) {
            float2 inner = make_float2(0.0f, 0.0f);
#pragma unroll
            for (int nl = 0; nl < 4; nl++)
                inner = cfma(sPB[l][ml * 4 + nl], cur[col * 16 + nh * 4 + nl], inner);
            acc = cfma(sPA[l][mh * 4 + nh], inner, acc);
        }
        nxt[col * 16 + mp] = acc;
        __syncthreads();
        float2* tmp = cur; cur = nxt; nxt = tmp;
    }

    {
        int j = t >> 4, k = t & 15;
        float hr = 0.0f, hi = 0.0f;
#pragma unroll
        for (int mm = 0; mm < 16; mm++) {
            float zz = ((mm >> 3) & 1) ? -1.0f : 1.0f;
            float2 uj = cur[j * 16 + mm], uk = cur[k * 16 + mm];
            hr += zz * (uj.x * uk.x + uj.y * uk.y);
            hi += zz * (uj.x * uk.y - uj.y * uk.x);
        }
        int q = (__popc(j) - __popc(k)) & 3;
        float gval = (q == 0) ? hr : (q == 1) ? -hi : (q == 2) ? -hr : hi;
        int gidx = 0;
#pragma unroll
        for (int wq = 0; wq < 4; wq++) {
            int bi = 3 - wq;
            int p = ((j >> bi) & 1) * 2 + ((k >> bi) & 1);
            gidx = gidx * 4 + p;
        }
        sG[gidx] = gval;
    }
    __syncthreads();

    const float V[4][3] = {{0.5f, 0.5f, 0.0f},
                           {0.0f, 0.0f, 0.5f},
                           {0.0f, 0.0f, 0.5f},
                           {0.5f, -0.5f, 0.0f}};
    if (t < 192) {
        int d = t % 3, p2 = (t / 3) & 3, p1 = (t / 12) & 3, p0 = t / 48;
        float acc = 0.0f;
#pragma unroll
        for (int p3 = 0; p3 < 4; p3++)
            acc += sG[((p0 * 4 + p1) * 4 + p2) * 4 + p3] * V[p3][d];
        sA1[t] = acc;
    }
    __syncthreads();
    if (t < 144) {
        int d = t % 3, c = (t / 3) % 3, rest = t / 9;
        int p1 = rest & 3, p0 = rest >> 2;
        float acc = 0.0f;
#pragma unroll
        for (int p2 = 0; p2 < 4; p2++)
            acc += sA1[((p0 * 4 + p1) * 4 + p2) * 3 + d] * V[p2][c];
        sA2[t] = acc;
    }
    __syncthreads();
    if (t < 108) {
        int d = t % 3, c = (t / 3) % 3, b = (t / 9) % 3, p0 = t / 27;
        float acc = 0.0f;
#pragma unroll
        for (int p1 = 0; p1 < 4; p1++)
            acc += sA2[((p0 * 4 + p1) * 3 + c) * 3 + d] * V[p1][b];
        sA1[t] = acc;
    }
    __syncthreads();
    if (t < 81) {
        int d = t % 3, c = (t / 3) % 3, b = (t / 9) % 3, a = t / 27;
        float acc = 0.0f;
#pragma unroll
        for (int p0 = 0; p0 < 4; p0++)
            acc += sA1[((p0 * 3 + b) * 3 + c) * 3 + d] * V[p0][a];
        g_T[(a * 9 + b * 3 + c) * 4 + d] = acc;
    } else if (t < 108) {
        g_T[(t - 81) * 4 + 3] = 0.0f;
    }
}

// Main: 4 consecutive samples/thread, E accumulated inline per-u (<=64 regs
// proven by R5), 4 CTAs/SM. One quad per thread, exact grid, no stride loop.
__global__ void __launch_bounds__(256, 4) vqc_main(const float4* __restrict__ x,
                                                   float* __restrict__ out, int n) {
    __shared__ __align__(16) float4 sT[28];
    if (threadIdx.x < 28) sT[threadIdx.x] = reinterpret_cast<const float4*>(g_T)[threadIdx.x];
    __syncthreads();

    const int quads = (n + 3) >> 2;
    const int q = blockIdx.x * 256 + threadIdx.x;
    if (q >= quads) return;
    const int base = q * 4;
    const bool full = (base + 3 < n);

    float c0[4], s0[4], c1[4], s1[4], c2[4], s2[4], c3[4], s3[4];
#pragma unroll
    for (int k = 0; k < 4; k++) {
        float4 v = (full || base + k < n) ? x[base + k]
                                          : make_float4(0.f, 0.f, 0.f, 0.f);
        __sincosf(v.x, &s0[k], &c0[k]);
        __sincosf(v.y, &s1[k], &c1[k]);
        __sincosf(v.z, &s2[k], &c2[k]);
        __sincosf(v.w, &s3[k], &c3[k]);
    }

    float E[4];
#pragma unroll
    for (int u = 0; u < 9; u++) {
        const float4 t0 = sT[u * 3 + 0];
        const float4 t1 = sT[u * 3 + 1];
        const float4 t2 = sT[u * 3 + 2];
        const int a = u / 3, b = u % 3;  // compile-time under unroll
#pragma unroll
        for (int k = 0; k < 4; k++) {
            float a0 = fmaf(t0.z, s3[k], fmaf(t0.y, c3[k], t0.x));
            float a1 = fmaf(t1.z, s3[k], fmaf(t1.y, c3[k], t1.x));
            float a2 = fmaf(t2.z, s3[k], fmaf(t2.y, c3[k], t2.x));
            float r  = fmaf(a2, s2[k], fmaf(a1, c2[k], a0));
            if (a == 0 && b == 0) {
                E[k] = r;
            } else if (a == 0) {
                E[k] = fmaf(r, (b == 1) ? c1[k] : s1[k], E[k]);
            } else if (b == 0) {
                E[k] = fmaf(r, (a == 1) ? c0[k] : s0[k], E[k]);
            } else {
                float f0v = (a == 1) ? c0[k] : s0[k];
                float f1v = (b == 1) ? c1[k] : s1[k];
                E[k] = fmaf(r * f0v, f1v, E[k]);
            }
        }
    }

    if (full) {
        reinterpret_cast<float4*>(out)[q] = make_float4(E[0], E[1], E[2], E[3]);
    } else {
#pragma unroll
        for (int k = 0; k < 4; k++)
            if (base + k < n) out[base + k] = E[k];
    }
}

extern "C" void kernel_launch(void* const* d_in, const int* in_sizes, int n_in,
                              void* d_out, int out_size) {
    const float* x = (const float*)d_in[0];        // (B, 4)
    const float* w = (const float*)d_in[1];        // (8, 4, 3)
    float* out = (float*)d_out;                    // (B,)
    int n = out_size;                              // B

    vqc_setup<<<1, 256>>>(w);
    int quads = (n + 3) / 4;
    vqc_main<<<(quads + 255) / 256, 256>>>((const float4*)x, out, n);
}